// round 2
// baseline (speedup 1.0000x reference)
#include <cuda_runtime.h>
#include <cuda_bf16.h>

// AGCBlock on GB300 — algebraic collapse.
//
// log_softmax over a singleton axis is exactly 0, so `context` == 0 for every
// patch, so the channel_add branch produces a single constant vector
//   term[C] = relu(LN(b1)) @ w2^T + b2
// identical for all 5184 patches. fold(unfold(x) + term)/counts == x + term[c]
// to ~1 ulp (every pixel is covered: stride 7 <= kernel 15).
// The whole problem is a 134 MB HBM stream: out = x + term[channel].

#define IMG   512
#define C_CH  64
#define P_CH  32
#define EPS_LN 1e-5f

#define HW        (IMG * IMG)         // 262144 elements per channel
#define HW4       (HW / 4)            // 65536 float4 per channel (pow2)
#define TOTAL4    (C_CH * HW4)        // 4194304 float4
#define THREADS   256
#define GRID      2048
#define STRIDE    (GRID * THREADS)    // 524288 = 8 * HW4  (exact division)
#define ITERS     (TOTAL4 / STRIDE)   // 8, no tail

__global__ __launch_bounds__(THREADS)
void agc_add_kernel(const float* __restrict__ x,
                    const float* __restrict__ b1,
                    const float* __restrict__ gamma,
                    const float* __restrict__ beta,
                    const float* __restrict__ w2,   // [C, P] row-major
                    const float* __restrict__ b2,
                    float* __restrict__ out)
{
    __shared__ float t_s[P_CH];
    __shared__ float term_s[C_CH];

    const int tid = threadIdx.x;

    // ---- prologue: compute term[64] (redundant per block, L2-hot, tiny) ----
    if (tid < 32) {
        float v = b1[tid];                       // P=32 == one warp
        float s = v;
        #pragma unroll
        for (int o = 16; o > 0; o >>= 1) s += __shfl_xor_sync(0xffffffffu, s, o);
        float mu = s * (1.0f / P_CH);
        float d = v - mu;
        float sq = d * d;
        #pragma unroll
        for (int o = 16; o > 0; o >>= 1) sq += __shfl_xor_sync(0xffffffffu, sq, o);
        float var = sq * (1.0f / P_CH);         // biased, as torch LayerNorm
        float tval = d * rsqrtf(var + EPS_LN) * gamma[tid] + beta[tid];
        t_s[tid] = fmaxf(tval, 0.0f);            // ReLU
    }
    __syncthreads();

    if (tid < C_CH) {
        float acc = b2[tid];
        const float* wrow = w2 + tid * P_CH;
        #pragma unroll
        for (int p = 0; p < P_CH; ++p)
            acc = fmaf(t_s[p], wrow[p], acc);
        term_s[tid] = acc;
    }
    __syncthreads();

    // ---- main stream: out = x + term[channel] ----
    // STRIDE == 8*HW4, so each of the 8 iterations lands in channel c0 + 8*k.
    // Fully unrolled: 8 independent LDG.128s front-batched (MLP_p1 = 8).
    const float4* __restrict__ x4 = reinterpret_cast<const float4*>(x);
    float4* __restrict__ o4 = reinterpret_cast<float4*>(out);

    const int i0 = blockIdx.x * THREADS + tid;
    const int c0 = i0 >> 16;                     // i0 / HW4 ; warp-uniform

    #pragma unroll
    for (int k = 0; k < ITERS; ++k) {
        const int i = i0 + k * STRIDE;
        const float t = term_s[c0 + 8 * k];
        float4 v = x4[i];
        v.x += t; v.y += t; v.z += t; v.w += t;
        o4[i] = v;
    }
}

extern "C" void kernel_launch(void* const* d_in, const int* in_sizes, int n_in,
                              void* d_out, int out_size)
{
    // metadata order: x, w_mask, b_mask, w1, b1, gamma, beta, w2, b2
    const float* x     = (const float*)d_in[0];
    const float* b1    = (const float*)d_in[4];
    const float* gamma = (const float*)d_in[5];
    const float* beta  = (const float*)d_in[6];
    const float* w2    = (const float*)d_in[7];
    const float* b2    = (const float*)d_in[8];
    float* out = (float*)d_out;

    agc_add_kernel<<<GRID, THREADS>>>(x, b1, gamma, beta, w2, b2, out);
}